// round 15
// baseline (speedup 1.0000x reference)
#include <cuda_runtime.h>
#include <cuda_bf16.h>
#include <math.h>
#include <stdint.h>

#define N_NODES 30000
#define N_REL   38
#define N_EDGE  200000
#define HID     64
#define PAD     68     // fp32 stage row stride
#define ASTR    72     // bf16 smem tile row stride
#define N_CHUNK 5

// ---------------- scratch ----------------
__device__ float g_AGG[(size_t)N_REL * N_NODES * HID];   // Σ w·emb[src] (memset 0)
__device__ float g_Ssrc[N_REL * N_NODES];
__device__ float g_Sdst[N_REL * N_NODES];
__device__ float g_DEN [N_REL * N_NODES];                // wself + Σ w
__device__ float g_WSELF[N_REL * N_NODES];               // wself (untouched by scatter)
__device__ float g_PREP[N_CHUNK][(size_t)N_NODES * HID];
__device__ float g_VS[N_REL * 64];
__device__ float g_VD[N_REL * 64];
__device__ float g_bx[64];                               // Σ_r bias[r] @ W1[r+1] (memset 0 + atomic)
__device__ __align__(16) __nv_bfloat16 g_MH  [(size_t)N_REL * 4096]; // (W@W1seg)^T hi
__device__ __align__(16) __nv_bfloat16 g_ML  [(size_t)N_REL * 4096];
__device__ __align__(16) __nv_bfloat16 g_W10H[4096];                 // W1seg0^T
__device__ __align__(16) __nv_bfloat16 g_W10L[4096];
__device__ __align__(16) __nv_bfloat16 g_W2H [4096];
__device__ __align__(16) __nv_bfloat16 g_W2L [4096];

__device__ __forceinline__ float lrelu(float x) { return x > 0.f ? x : 0.2f * x; }
__device__ __forceinline__ void split1(float x, __nv_bfloat16& h, __nv_bfloat16& l) {
    h = __float2bfloat16(x);
    l = __float2bfloat16(x - __bfloat162float(h));
}
__device__ __forceinline__ uint32_t pk(__nv_bfloat16 a, __nv_bfloat16 b) {
    __nv_bfloat162 v; v.x = a; v.y = b;
    return *(uint32_t*)&v;
}

// ---------------- mma.sync m16n8k16 bf16 ----------------
__device__ __forceinline__ void mma16816(float* d, const uint32_t* a, uint32_t b0, uint32_t b1) {
    asm volatile(
        "mma.sync.aligned.m16n8k16.row.col.f32.bf16.bf16.f32 "
        "{%0,%1,%2,%3}, {%4,%5,%6,%7}, {%8,%9}, {%0,%1,%2,%3};"
        : "+f"(d[0]), "+f"(d[1]), "+f"(d[2]), "+f"(d[3])
        : "r"(a[0]), "r"(a[1]), "r"(a[2]), "r"(a[3]), "r"(b0), "r"(b1));
}
__device__ __forceinline__ void lda_frag(uint32_t* a, const __nv_bfloat16* T,
                                         int wr, int j0, int g, int t) {
    a[0] = *(const uint32_t*)&T[(wr + g)     * ASTR + j0 + 2 * t];
    a[1] = *(const uint32_t*)&T[(wr + g + 8) * ASTR + j0 + 2 * t];
    a[2] = *(const uint32_t*)&T[(wr + g)     * ASTR + j0 + 2 * t + 8];
    a[3] = *(const uint32_t*)&T[(wr + g + 8) * ASTR + j0 + 2 * t + 8];
}
__device__ __forceinline__ void warp_mma_3term(
    const __nv_bfloat16* Ah, const __nv_bfloat16* Al,
    const __nv_bfloat16* Bh, const __nv_bfloat16* Bl,
    int wr, int g, int t, float acc[8][4])
{
#pragma unroll
    for (int kc = 0; kc < 4; ++kc) {
        const int j0 = kc * 16;
        uint32_t ah[4], al[4];
        lda_frag(ah, Ah, wr, j0, g, t);
        lda_frag(al, Al, wr, j0, g, t);
#pragma unroll
        for (int nt = 0; nt < 8; ++nt) {
            const int c = nt * 8 + g;
            uint32_t bh0 = *(const uint32_t*)&Bh[c * ASTR + j0 + 2 * t];
            uint32_t bh1 = *(const uint32_t*)&Bh[c * ASTR + j0 + 2 * t + 8];
            uint32_t bl0 = *(const uint32_t*)&Bl[c * ASTR + j0 + 2 * t];
            uint32_t bl1 = *(const uint32_t*)&Bl[c * ASTR + j0 + 2 * t + 8];
            mma16816(acc[nt], ah, bh0, bh1);
            mma16816(acc[nt], al, bh0, bh1);
            mma16816(acc[nt], ah, bl0, bl1);
        }
    }
}
__device__ __forceinline__ void acc_to_stage(float* stage, const float acc[8][4],
                                             int wr, int g, int t) {
#pragma unroll
    for (int nt = 0; nt < 8; ++nt) {
        *(float2*)&stage[(wr + g)     * PAD + nt * 8 + 2 * t] = make_float2(acc[nt][0], acc[nt][1]);
        *(float2*)&stage[(wr + g + 8) * PAD + nt * 8 + 2 * t] = make_float2(acc[nt][2], acc[nt][3]);
    }
}

// ---------------- fused prep: blocks 0..37 = M/VS/VD/bx for rel; block 38 = W10+W2 ----------------
__global__ __launch_bounds__(256) void prep_all(
    const float* __restrict__ W, const float* __restrict__ W1,
    const float* __restrict__ W2, const float* __restrict__ as_,
    const float* __restrict__ ad_, const float* __restrict__ bias)
{
    __shared__ float sW[4096], sW1[4096];
    const int rel = blockIdx.x, tid = threadIdx.x;
    if (rel < N_REL) {
        for (int i = tid; i < 1024; i += 256) {
            ((float4*)sW)[i]  = ((const float4*)(W  + (size_t)rel * 4096))[i];
            ((float4*)sW1)[i] = ((const float4*)(W1 + (size_t)(rel + 1) * 4096))[i];
        }
        __syncthreads();
        // M[r] = W[r] @ W1[r+1], stored transposed bf16 hi/lo
        const int i = tid >> 2, jb = (tid & 3) * 16;
        float m[16];
#pragma unroll
        for (int j = 0; j < 16; ++j) m[j] = 0.f;
        for (int h = 0; h < 64; ++h) {
            float wv = sW[i * 64 + h];
#pragma unroll
            for (int j = 0; j < 16; ++j) m[j] += wv * sW1[h * 64 + jb + j];
        }
#pragma unroll
        for (int j = 0; j < 16; ++j) {
            __nv_bfloat16 hh, ll;
            split1(m[j], hh, ll);
            g_MH[(size_t)rel * 4096 + (jb + j) * 64 + i] = hh;
            g_ML[(size_t)rel * 4096 + (jb + j) * 64 + i] = ll;
        }
        // VS/VD (threads 0-63)
        if (tid < 64) {
            float s = 0.f, d = 0.f;
#pragma unroll 8
            for (int h = 0; h < 64; ++h) {
                float w = sW[tid * 64 + h];
                s += w * as_[rel * 64 + h];
                d += w * ad_[rel * 64 + h];
            }
            g_VS[rel * 64 + tid] = s;
            g_VD[rel * 64 + tid] = d;
        }
        // bx partial (threads 64-127): Σ_h bias[r][h]*W1[r+1][h][j]
        if (tid >= 64 && tid < 128) {
            int j = tid - 64;
            float p = 0.f;
#pragma unroll 8
            for (int h = 0; h < 64; ++h)
                p += bias[rel * 64 + h] * sW1[h * 64 + j];
            atomicAdd(&g_bx[j], p);
        }
    } else {
        for (int i = tid; i < 4096; i += 256) {
            int c = i >> 6, j = i & 63;
            split1(W1[(j << 6) + c], g_W10H[i], g_W10L[i]);
            split1(W2[(j << 6) + c], g_W2H[i],  g_W2L[i]);
        }
    }
}

// ---------------- s_den: scores + wself only (no bulk writes) ----------------
__global__ __launch_bounds__(256) void s_den(const float* __restrict__ emb) {
    __shared__ float sVs[64], sVd[64];
    const int rel = blockIdx.y;
    if (threadIdx.x < 64) {
        sVs[threadIdx.x] = g_VS[rel * 64 + threadIdx.x];
        sVd[threadIdx.x] = g_VD[rel * 64 + threadIdx.x];
    }
    __syncthreads();
    const int idx  = blockIdx.x * 256 + threadIdx.x;
    const int node = idx >> 2, q = idx & 3;
    float ss = 0.f, sd = 0.f;
    if (node < N_NODES) {
        const float* er = &emb[(size_t)node * 64 + q * 16];
#pragma unroll
        for (int u = 0; u < 16; ++u) {
            float e = er[u];
            ss += e * sVs[q * 16 + u];
            sd += e * sVd[q * 16 + u];
        }
    }
    ss += __shfl_xor_sync(0xffffffffu, ss, 1);
    sd += __shfl_xor_sync(0xffffffffu, sd, 1);
    ss += __shfl_xor_sync(0xffffffffu, ss, 2);
    sd += __shfl_xor_sync(0xffffffffu, sd, 2);
    if (q == 0 && node < N_NODES) {
        float wself = __expf(lrelu(ss + sd));
        g_Ssrc [rel * N_NODES + node] = ss;
        g_Sdst [rel * N_NODES + node] = sd;
        g_DEN  [rel * N_NODES + node] = wself;
        g_WSELF[rel * N_NODES + node] = wself;
    }
}

// ---------------- scatter: AGG[dst] += w*emb[src], DEN[dst] += w ----------------
// 4 lanes/edge, 4x(LDG.128 + RED.128) per lane. Exact grid: N_EDGE*4 = 3125*256.
__global__ __launch_bounds__(256) void scatter_kernel(const int* __restrict__ edges,
                                                      const float* __restrict__ emb, int rel0) {
    const int rel  = rel0 + blockIdx.y;
    const int t    = blockIdx.x * 256 + threadIdx.x;
    const int edge = t >> 2;
    const int sub  = threadIdx.x & 3;

    const int* eb = edges + (size_t)rel * 2 * N_EDGE;
    const int s = __ldg(&eb[edge]);
    const int d = __ldg(&eb[N_EDGE + edge]);
    float e = lrelu(__ldg(&g_Ssrc[rel * N_NODES + s]) + __ldg(&g_Sdst[rel * N_NODES + d]));
    float w = __expf(e);
    if (sub == 0) atomicAdd(&g_DEN[rel * N_NODES + d], w);

    const float* sp = &emb[(size_t)s * 64 + sub * 16];
    float*       op = &g_AGG[((size_t)rel * N_NODES + d) * 64 + sub * 16];
    float4 h0 = *(const float4*)(sp);
    float4 h1 = *(const float4*)(sp + 4);
    float4 h2 = *(const float4*)(sp + 8);
    float4 h3 = *(const float4*)(sp + 12);
    asm volatile("red.global.add.v4.f32 [%0], {%1,%2,%3,%4};"
                 :: "l"(op), "f"(w * h0.x), "f"(w * h0.y), "f"(w * h0.z), "f"(w * h0.w) : "memory");
    asm volatile("red.global.add.v4.f32 [%0], {%1,%2,%3,%4};"
                 :: "l"(op + 4), "f"(w * h1.x), "f"(w * h1.y), "f"(w * h1.z), "f"(w * h1.w) : "memory");
    asm volatile("red.global.add.v4.f32 [%0], {%1,%2,%3,%4};"
                 :: "l"(op + 8), "f"(w * h2.x), "f"(w * h2.y), "f"(w * h2.z), "f"(w * h2.w) : "memory");
    asm volatile("red.global.add.v4.f32 [%0], {%1,%2,%3,%4};"
                 :: "l"(op + 12), "f"(w * h3.x), "f"(w * h3.y), "f"(w * h3.z), "f"(w * h3.w) : "memory");
}

// ---------------- final_acc: partial pre-tanh sums; self-loop folded into A-build ----------------
__global__ __launch_bounds__(256) void final_acc(
    const float* __restrict__ emb, const int* __restrict__ nodes)
{
    extern __shared__ char sm[];
    __nv_bfloat16* Ah = (__nv_bfloat16*)sm;
    __nv_bfloat16* Al = Ah + 128 * ASTR;
    __nv_bfloat16* Bh = Al + 128 * ASTR;
    __nv_bfloat16* Bl = Bh + 64 * ASTR;
    float* stage = (float*)sm;
    __shared__ float sInv[128], sWs[128];
    __shared__ int   sNd[128];

    const int chunk = blockIdx.y;
    const int seg0  = chunk * 8;
    const int seg1  = (seg0 + 8 < N_REL + 1) ? seg0 + 8 : N_REL + 1;
    const int n0  = blockIdx.x * 128;
    const int tid = threadIdx.x;
    const int wid = tid >> 5, lane = tid & 31, g = lane >> 2, t = lane & 3;

    if (tid < 128) {
        int nn = n0 + tid;
        sNd[tid] = (nn < N_NODES) ? nodes[nn] : -1;
    }

    float acc[8][4];
#pragma unroll
    for (int nt = 0; nt < 8; ++nt)
#pragma unroll
        for (int q = 0; q < 4; ++q) acc[nt][q] = 0.f;

    for (int seg = seg0; seg < seg1; ++seg) {
        __syncthreads();
        const char* bhSrc = (seg == 0) ? (const char*)g_W10H
                                       : (const char*)g_MH + (size_t)(seg - 1) * 8192;
        const char* blSrc = (seg == 0) ? (const char*)g_W10L
                                       : (const char*)g_ML + (size_t)(seg - 1) * 8192;
        for (int i = tid; i < 512; i += 256) {
            int row = i >> 3, c16 = (i & 7) * 16;
            *(uint4*)((char*)Bh + row * 144 + c16) = *(const uint4*)(bhSrc + row * 128 + c16);
            *(uint4*)((char*)Bl + row * 144 + c16) = *(const uint4*)(blSrc + row * 128 + c16);
        }
        if (seg > 0 && tid < 128) {
            int nd = sNd[tid];
            if (nd >= 0) {
                sInv[tid] = 1.f / g_DEN[(seg - 1) * N_NODES + nd];
                sWs[tid]  = g_WSELF[(seg - 1) * N_NODES + nd];
            } else {
                sInv[tid] = 0.f; sWs[tid] = 0.f;
            }
        }
        __syncthreads();

        for (int i = tid; i < 2048; i += 256) {
            int row = i >> 4, k4 = (i & 15) * 4;
            int nd = sNd[row];
            float4 v = make_float4(0.f, 0.f, 0.f, 0.f);
            if (nd >= 0) {
                float4 e = *(const float4*)&emb[(size_t)nd * 64 + k4];
                if (seg == 0) {
                    v = e;
                } else {
                    const int r = seg - 1;
                    float4 o = *(const float4*)&g_AGG[((size_t)r * N_NODES + nd) * 64 + k4];
                    float inv = sInv[row], wsf = sWs[row];
                    v.x = (o.x + wsf * e.x) * inv;
                    v.y = (o.y + wsf * e.y) * inv;
                    v.z = (o.z + wsf * e.z) * inv;
                    v.w = (o.w + wsf * e.w) * inv;
                }
            }
            __nv_bfloat16 h0, l0, h1, l1, h2, l2, h3, l3;
            split1(v.x, h0, l0); split1(v.y, h1, l1);
            split1(v.z, h2, l2); split1(v.w, h3, l3);
            *(uint2*)((char*)Ah + row * 144 + k4 * 2) = make_uint2(pk(h0, h1), pk(h2, h3));
            *(uint2*)((char*)Al + row * 144 + k4 * 2) = make_uint2(pk(l0, l1), pk(l2, l3));
        }
        __syncthreads();

        warp_mma_3term(Ah, Al, Bh, Bl, wid * 16, g, t, acc);
    }
    __syncthreads();

    acc_to_stage(stage, acc, wid * 16, g, t);
    __syncthreads();

    float* prep = g_PREP[chunk];
    for (int i = tid; i < 2048; i += 256) {
        int row = i >> 4, q = i & 15;
        int nn = n0 + row;
        if (nn < N_NODES)
            *(float4*)&prep[(size_t)nn * 64 + q * 4] = *(float4*)&stage[row * PAD + q * 4];
    }
}

// ---------------- final_finish: sum partials + b1 + bx, tanh, @W2 + b2 ----------------
__global__ __launch_bounds__(256) void final_finish(
    const float* __restrict__ b1, const float* __restrict__ b2, float* __restrict__ out)
{
    extern __shared__ char sm[];
    __nv_bfloat16* Ah = (__nv_bfloat16*)sm;
    __nv_bfloat16* Al = Ah + 128 * ASTR;
    __nv_bfloat16* Bh = Al + 128 * ASTR;
    __nv_bfloat16* Bl = Bh + 64 * ASTR;
    float* stage = (float*)sm;

    const int n0  = blockIdx.x * 128;
    const int tid = threadIdx.x;
    const int wid = tid >> 5, lane = tid & 31, g = lane >> 2, t = lane & 3;

    for (int i = tid; i < 512; i += 256) {
        int row = i >> 3, c16 = (i & 7) * 16;
        *(uint4*)((char*)Bh + row * 144 + c16) =
            *(const uint4*)((const char*)g_W2H + row * 128 + c16);
        *(uint4*)((char*)Bl + row * 144 + c16) =
            *(const uint4*)((const char*)g_W2L + row * 128 + c16);
    }

    for (int i = tid; i < 2048; i += 256) {
        int row = i >> 4, k4 = (i & 15) * 4;
        int nn = n0 + row;
        float4 v = make_float4(0.f, 0.f, 0.f, 0.f);
        if (nn < N_NODES) {
            size_t off = (size_t)nn * 64 + k4;
#pragma unroll
            for (int c = 0; c < N_CHUNK; ++c) {
                float4 p = *(const float4*)&g_PREP[c][off];
                v.x += p.x; v.y += p.y; v.z += p.z; v.w += p.w;
            }
            float4 bb = *(const float4*)&b1[k4];
            float4 bx = *(const float4*)&g_bx[k4];
            v.x = tanhf(v.x + bb.x + bx.x); v.y = tanhf(v.y + bb.y + bx.y);
            v.z = tanhf(v.z + bb.z + bx.z); v.w = tanhf(v.w + bb.w + bx.w);
        }
        __nv_bfloat16 h0, l0, h1, l1, h2, l2, h3, l3;
        split1(v.x, h0, l0); split1(v.y, h1, l1);
        split1(v.z, h2, l2); split1(v.w, h3, l3);
        *(uint2*)((char*)Ah + row * 144 + k4 * 2) = make_uint2(pk(h0, h1), pk(h2, h3));
        *(uint2*)((char*)Al + row * 144 + k4 * 2) = make_uint2(pk(l0, l1), pk(l2, l3));
    }
    __syncthreads();

    float acc[8][4];
#pragma unroll
    for (int nt = 0; nt < 8; ++nt)
#pragma unroll
        for (int q = 0; q < 4; ++q) acc[nt][q] = 0.f;

    warp_mma_3term(Ah, Al, Bh, Bl, wid * 16, g, t, acc);
    __syncthreads();

    acc_to_stage(stage, acc, wid * 16, g, t);
    __syncthreads();

    for (int i = tid; i < 2048; i += 256) {
        int row = i >> 4, q = i & 15;
        int nn = n0 + row;
        if (nn < N_NODES) {
            float4 v  = *(float4*)&stage[row * PAD + q * 4];
            float4 bb = *(const float4*)&b2[q * 4];
            *(float4*)&out[(size_t)nn * 64 + q * 4] =
                make_float4(v.x + bb.x, v.y + bb.y, v.z + bb.z, v.w + bb.w);
        }
    }
}

// ---------------- launch ----------------
extern "C" void kernel_launch(void* const* d_in, const int* in_sizes, int n_in,
                              void* d_out, int out_size) {
    const float* emb     = (const float*)d_in[0];
    const float* W       = (const float*)d_in[1];
    const float* att_src = (const float*)d_in[2];
    const float* att_dst = (const float*)d_in[3];
    const float* bias    = (const float*)d_in[4];
    const float* W1      = (const float*)d_in[5];
    const float* b1      = (const float*)d_in[6];
    const float* W2      = (const float*)d_in[7];
    const float* b2      = (const float*)d_in[8];
    const int*   edges   = (const int*)d_in[9];
    const int*   nodes   = (const int*)d_in[10];
    float*       out     = (float*)d_out;

    const int MMA_SMEM = (128 * ASTR + 128 * ASTR + 64 * ASTR + 64 * ASTR) * 2;  // 55296
    cudaFuncSetAttribute(final_acc,    cudaFuncAttributeMaxDynamicSharedMemorySize, MMA_SMEM);
    cudaFuncSetAttribute(final_finish, cudaFuncAttributeMaxDynamicSharedMemorySize, MMA_SMEM);

    void *pAGG = nullptr, *pBX = nullptr;
    cudaGetSymbolAddress(&pAGG, g_AGG);
    cudaGetSymbolAddress(&pBX, g_bx);
    cudaMemsetAsync(pAGG, 0, sizeof(float) * (size_t)N_REL * N_NODES * HID, 0);
    cudaMemsetAsync(pBX,  0, 64 * sizeof(float), 0);

    prep_all<<<N_REL + 1, 256>>>(W, W1, W2, att_src, att_dst, bias);

    dim3 gsd((N_NODES * 4 + 255) / 256, N_REL);
    s_den<<<gsd, 256>>>(emb);

    // 4 lanes/edge; 4 launches of ~10 relations (ncu -s 5 lands on a scatter)
    dim3 gs(N_EDGE * 4 / 256, 10);
    scatter_kernel<<<gs, 256>>>(edges, emb, 0);
    scatter_kernel<<<gs, 256>>>(edges, emb, 10);
    scatter_kernel<<<gs, 256>>>(edges, emb, 20);
    dim3 gs2(N_EDGE * 4 / 256, 8);
    scatter_kernel<<<gs2, 256>>>(edges, emb, 30);

    const int nb = (N_NODES + 127) / 128;   // 235
    dim3 gacc(nb, N_CHUNK);
    final_acc<<<gacc, 256, MMA_SMEM>>>(emb, nodes);
    final_finish<<<nb, 256, MMA_SMEM>>>(b1, b2, out);
}

// round 16
// speedup vs baseline: 1.4296x; 1.4296x over previous
#include <cuda_runtime.h>
#include <cuda_bf16.h>
#include <math.h>
#include <stdint.h>

#define N_NODES 30000
#define N_REL   38
#define N_EDGE  200000
#define HID     64
#define PAD     68     // fp32 stage row stride
#define ASTR    72     // bf16 smem tile row stride
#define N_CHUNK 5
#define MAXD    64     // slot capacity per (rel, dst); Poisson(6.7) overflow ~1e-40

// ---------------- scratch ----------------
__device__ float g_AGG[(size_t)N_REL * N_NODES * HID];   // written fully by gather
__device__ float g_Ssrc[N_REL * N_NODES];
__device__ float g_Sdst[N_REL * N_NODES];
__device__ float g_DEN [N_REL * N_NODES];                // wself (s_den) -> full den (gather)
__device__ float g_PREP[N_CHUNK][(size_t)N_NODES * HID];
__device__ int   g_cnt [N_REL * N_NODES];                // slot cursor (memset 0)
__device__ int2  g_slot[(size_t)N_REL * N_NODES * MAXD]; // (src, w) buckets
__device__ float g_VS[N_REL * 64];
__device__ float g_VD[N_REL * 64];
__device__ float g_bx[64];                               // Σ_r bias[r] @ W1[r+1]
__device__ __align__(16) __nv_bfloat16 g_MH  [(size_t)N_REL * 4096]; // (W@W1seg)^T hi
__device__ __align__(16) __nv_bfloat16 g_ML  [(size_t)N_REL * 4096];
__device__ __align__(16) __nv_bfloat16 g_W10H[4096];                 // W1seg0^T
__device__ __align__(16) __nv_bfloat16 g_W10L[4096];
__device__ __align__(16) __nv_bfloat16 g_W2H [4096];
__device__ __align__(16) __nv_bfloat16 g_W2L [4096];

__device__ __forceinline__ float lrelu(float x) { return x > 0.f ? x : 0.2f * x; }
__device__ __forceinline__ void split1(float x, __nv_bfloat16& h, __nv_bfloat16& l) {
    h = __float2bfloat16(x);
    l = __float2bfloat16(x - __bfloat162float(h));
}
__device__ __forceinline__ uint32_t pk(__nv_bfloat16 a, __nv_bfloat16 b) {
    __nv_bfloat162 v; v.x = a; v.y = b;
    return *(uint32_t*)&v;
}

// ---------------- mma.sync m16n8k16 bf16 ----------------
__device__ __forceinline__ void mma16816(float* d, const uint32_t* a, uint32_t b0, uint32_t b1) {
    asm volatile(
        "mma.sync.aligned.m16n8k16.row.col.f32.bf16.bf16.f32 "
        "{%0,%1,%2,%3}, {%4,%5,%6,%7}, {%8,%9}, {%0,%1,%2,%3};"
        : "+f"(d[0]), "+f"(d[1]), "+f"(d[2]), "+f"(d[3])
        : "r"(a[0]), "r"(a[1]), "r"(a[2]), "r"(a[3]), "r"(b0), "r"(b1));
}
__device__ __forceinline__ void lda_frag(uint32_t* a, const __nv_bfloat16* T,
                                         int wr, int j0, int g, int t) {
    a[0] = *(const uint32_t*)&T[(wr + g)     * ASTR + j0 + 2 * t];
    a[1] = *(const uint32_t*)&T[(wr + g + 8) * ASTR + j0 + 2 * t];
    a[2] = *(const uint32_t*)&T[(wr + g)     * ASTR + j0 + 2 * t + 8];
    a[3] = *(const uint32_t*)&T[(wr + g + 8) * ASTR + j0 + 2 * t + 8];
}
__device__ __forceinline__ void warp_mma_3term(
    const __nv_bfloat16* Ah, const __nv_bfloat16* Al,
    const __nv_bfloat16* Bh, const __nv_bfloat16* Bl,
    int wr, int g, int t, float acc[8][4])
{
#pragma unroll
    for (int kc = 0; kc < 4; ++kc) {
        const int j0 = kc * 16;
        uint32_t ah[4], al[4];
        lda_frag(ah, Ah, wr, j0, g, t);
        lda_frag(al, Al, wr, j0, g, t);
#pragma unroll
        for (int nt = 0; nt < 8; ++nt) {
            const int c = nt * 8 + g;
            uint32_t bh0 = *(const uint32_t*)&Bh[c * ASTR + j0 + 2 * t];
            uint32_t bh1 = *(const uint32_t*)&Bh[c * ASTR + j0 + 2 * t + 8];
            uint32_t bl0 = *(const uint32_t*)&Bl[c * ASTR + j0 + 2 * t];
            uint32_t bl1 = *(const uint32_t*)&Bl[c * ASTR + j0 + 2 * t + 8];
            mma16816(acc[nt], ah, bh0, bh1);
            mma16816(acc[nt], al, bh0, bh1);
            mma16816(acc[nt], ah, bl0, bl1);
        }
    }
}
__device__ __forceinline__ void acc_to_stage(float* stage, const float acc[8][4],
                                             int wr, int g, int t) {
#pragma unroll
    for (int nt = 0; nt < 8; ++nt) {
        *(float2*)&stage[(wr + g)     * PAD + nt * 8 + 2 * t] = make_float2(acc[nt][0], acc[nt][1]);
        *(float2*)&stage[(wr + g + 8) * PAD + nt * 8 + 2 * t] = make_float2(acc[nt][2], acc[nt][3]);
    }
}

// ---------------- fused prep: blocks 0..37 = M/VS/VD/bx; block 38 = W10+W2 ----------------
__global__ __launch_bounds__(256) void prep_all(
    const float* __restrict__ W, const float* __restrict__ W1,
    const float* __restrict__ W2, const float* __restrict__ as_,
    const float* __restrict__ ad_, const float* __restrict__ bias)
{
    __shared__ float sW[4096], sW1[4096];
    const int rel = blockIdx.x, tid = threadIdx.x;
    if (rel < N_REL) {
        for (int i = tid; i < 1024; i += 256) {
            ((float4*)sW)[i]  = ((const float4*)(W  + (size_t)rel * 4096))[i];
            ((float4*)sW1)[i] = ((const float4*)(W1 + (size_t)(rel + 1) * 4096))[i];
        }
        __syncthreads();
        const int i = tid >> 2, jb = (tid & 3) * 16;
        float m[16];
#pragma unroll
        for (int j = 0; j < 16; ++j) m[j] = 0.f;
        for (int h = 0; h < 64; ++h) {
            float wv = sW[i * 64 + h];
#pragma unroll
            for (int j = 0; j < 16; ++j) m[j] += wv * sW1[h * 64 + jb + j];
        }
#pragma unroll
        for (int j = 0; j < 16; ++j) {
            __nv_bfloat16 hh, ll;
            split1(m[j], hh, ll);
            g_MH[(size_t)rel * 4096 + (jb + j) * 64 + i] = hh;
            g_ML[(size_t)rel * 4096 + (jb + j) * 64 + i] = ll;
        }
        if (tid < 64) {
            float s = 0.f, d = 0.f;
#pragma unroll 8
            for (int h = 0; h < 64; ++h) {
                float w = sW[tid * 64 + h];
                s += w * as_[rel * 64 + h];
                d += w * ad_[rel * 64 + h];
            }
            g_VS[rel * 64 + tid] = s;
            g_VD[rel * 64 + tid] = d;
        }
        if (tid >= 64 && tid < 128) {
            int j = tid - 64;
            float p = 0.f;
#pragma unroll 8
            for (int h = 0; h < 64; ++h)
                p += bias[rel * 64 + h] * sW1[h * 64 + j];
            atomicAdd(&g_bx[j], p);
        }
    } else {
        for (int i = tid; i < 4096; i += 256) {
            int c = i >> 6, j = i & 63;
            split1(W1[(j << 6) + c], g_W10H[i], g_W10L[i]);
            split1(W2[(j << 6) + c], g_W2H[i],  g_W2L[i]);
        }
    }
}

// ---------------- s_den: scores + wself ----------------
__global__ __launch_bounds__(256) void s_den(const float* __restrict__ emb) {
    __shared__ float sVs[64], sVd[64];
    const int rel = blockIdx.y;
    if (threadIdx.x < 64) {
        sVs[threadIdx.x] = g_VS[rel * 64 + threadIdx.x];
        sVd[threadIdx.x] = g_VD[rel * 64 + threadIdx.x];
    }
    __syncthreads();
    const int idx  = blockIdx.x * 256 + threadIdx.x;
    const int node = idx >> 2, q = idx & 3;
    float ss = 0.f, sd = 0.f;
    if (node < N_NODES) {
        const float* er = &emb[(size_t)node * 64 + q * 16];
#pragma unroll
        for (int u = 0; u < 16; ++u) {
            float e = er[u];
            ss += e * sVs[q * 16 + u];
            sd += e * sVd[q * 16 + u];
        }
    }
    ss += __shfl_xor_sync(0xffffffffu, ss, 1);
    sd += __shfl_xor_sync(0xffffffffu, sd, 1);
    ss += __shfl_xor_sync(0xffffffffu, ss, 2);
    sd += __shfl_xor_sync(0xffffffffu, sd, 2);
    if (q == 0 && node < N_NODES) {
        g_Ssrc[rel * N_NODES + node] = ss;
        g_Sdst[rel * N_NODES + node] = sd;
        g_DEN [rel * N_NODES + node] = __expf(lrelu(ss + sd));   // wself seed
    }
}

// ---------------- fill: bucket (src, w) by dst ----------------
__global__ __launch_bounds__(256) void fill_kernel(const int* __restrict__ edges) {
    const int rel  = blockIdx.y;
    const int edge = blockIdx.x * 256 + threadIdx.x;
    if (edge < N_EDGE) {
        const int* eb = edges + (size_t)rel * 2 * N_EDGE;
        int s = __ldg(&eb[edge]);
        int d = __ldg(&eb[N_EDGE + edge]);
        float w = __expf(lrelu(__ldg(&g_Ssrc[rel * N_NODES + s]) +
                               __ldg(&g_Sdst[rel * N_NODES + d])));
        int base = rel * N_NODES + d;
        int pos = atomicAdd(&g_cnt[base], 1);
        if (pos < MAXD)
            g_slot[(size_t)base * MAXD + pos] = make_int2(s, __float_as_int(w));
    }
}

// ---------------- gather: AGG[n] = wself*emb[n] + Σ w*emb[src]; DEN[n] = wself + Σ w ----------------
// 8 lanes per node, 32 nodes per block. No atomics, coalesced 256B stores.
__global__ __launch_bounds__(256) void gather_kernel(const float* __restrict__ emb) {
    const int rel  = blockIdx.y;
    const int node = blockIdx.x * 32 + (threadIdx.x >> 3);
    const int sub  = threadIdx.x & 7;
    if (node >= N_NODES) return;

    const int base = rel * N_NODES + node;
    int cnt = __ldg(&g_cnt[base]);
    if (cnt > MAXD) cnt = MAXD;
    const float wself = __ldg(&g_DEN[base]);

    const float* er = &emb[(size_t)node * 64 + sub * 8];
    float4 e0 = *(const float4*)er;
    float4 e1 = *(const float4*)(er + 4);
    float4 a0 = make_float4(wself * e0.x, wself * e0.y, wself * e0.z, wself * e0.w);
    float4 a1 = make_float4(wself * e1.x, wself * e1.y, wself * e1.z, wself * e1.w);
    float den = wself;

    const int2* sp = &g_slot[(size_t)base * MAXD];
#pragma unroll 2
    for (int i = 0; i < cnt; ++i) {
        int2 e = __ldg(&sp[i]);
        float w = __int_as_float(e.y);
        const float* hr = &emb[(size_t)e.x * 64 + sub * 8];
        float4 h0 = *(const float4*)hr;
        float4 h1 = *(const float4*)(hr + 4);
        a0.x += w * h0.x; a0.y += w * h0.y; a0.z += w * h0.z; a0.w += w * h0.w;
        a1.x += w * h1.x; a1.y += w * h1.y; a1.z += w * h1.z; a1.w += w * h1.w;
        den += w;
    }

    float* ab = &g_AGG[(size_t)base * 64 + sub * 8];
    *(float4*)ab       = a0;
    *(float4*)(ab + 4) = a1;
    if (sub == 0) g_DEN[base] = den;
}

// ---------------- final_acc: partial pre-tanh sums over an 8-seg chunk ----------------
__global__ __launch_bounds__(256) void final_acc(
    const float* __restrict__ emb, const int* __restrict__ nodes)
{
    extern __shared__ char sm[];
    __nv_bfloat16* Ah = (__nv_bfloat16*)sm;
    __nv_bfloat16* Al = Ah + 128 * ASTR;
    __nv_bfloat16* Bh = Al + 128 * ASTR;
    __nv_bfloat16* Bl = Bh + 64 * ASTR;
    float* stage = (float*)sm;
    __shared__ float sInv[128];
    __shared__ int   sNd[128];

    const int chunk = blockIdx.y;
    const int seg0  = chunk * 8;
    const int seg1  = (seg0 + 8 < N_REL + 1) ? seg0 + 8 : N_REL + 1;
    const int n0  = blockIdx.x * 128;
    const int tid = threadIdx.x;
    const int wid = tid >> 5, lane = tid & 31, g = lane >> 2, t = lane & 3;

    if (tid < 128) {
        int nn = n0 + tid;
        sNd[tid] = (nn < N_NODES) ? nodes[nn] : -1;
    }

    float acc[8][4];
#pragma unroll
    for (int nt = 0; nt < 8; ++nt)
#pragma unroll
        for (int q = 0; q < 4; ++q) acc[nt][q] = 0.f;

    for (int seg = seg0; seg < seg1; ++seg) {
        __syncthreads();
        const char* bhSrc = (seg == 0) ? (const char*)g_W10H
                                       : (const char*)g_MH + (size_t)(seg - 1) * 8192;
        const char* blSrc = (seg == 0) ? (const char*)g_W10L
                                       : (const char*)g_ML + (size_t)(seg - 1) * 8192;
        for (int i = tid; i < 512; i += 256) {
            int row = i >> 3, c16 = (i & 7) * 16;
            *(uint4*)((char*)Bh + row * 144 + c16) = *(const uint4*)(bhSrc + row * 128 + c16);
            *(uint4*)((char*)Bl + row * 144 + c16) = *(const uint4*)(blSrc + row * 128 + c16);
        }
        if (seg > 0 && tid < 128) {
            int nd = sNd[tid];
            sInv[tid] = (nd >= 0) ? (1.f / g_DEN[(seg - 1) * N_NODES + nd]) : 0.f;
        }
        __syncthreads();

        for (int i = tid; i < 2048; i += 256) {
            int row = i >> 4, k4 = (i & 15) * 4;
            int nd = sNd[row];
            float4 v = make_float4(0.f, 0.f, 0.f, 0.f);
            if (nd >= 0) {
                if (seg == 0) {
                    v = *(const float4*)&emb[(size_t)nd * 64 + k4];
                } else {
                    const int r = seg - 1;
                    float4 o = *(const float4*)&g_AGG[((size_t)r * N_NODES + nd) * 64 + k4];
                    float inv = sInv[row];
                    v.x = o.x * inv; v.y = o.y * inv;
                    v.z = o.z * inv; v.w = o.w * inv;
                }
            }
            __nv_bfloat16 h0, l0, h1, l1, h2, l2, h3, l3;
            split1(v.x, h0, l0); split1(v.y, h1, l1);
            split1(v.z, h2, l2); split1(v.w, h3, l3);
            *(uint2*)((char*)Ah + row * 144 + k4 * 2) = make_uint2(pk(h0, h1), pk(h2, h3));
            *(uint2*)((char*)Al + row * 144 + k4 * 2) = make_uint2(pk(l0, l1), pk(l2, l3));
        }
        __syncthreads();

        warp_mma_3term(Ah, Al, Bh, Bl, wid * 16, g, t, acc);
    }
    __syncthreads();

    acc_to_stage(stage, acc, wid * 16, g, t);
    __syncthreads();

    float* prep = g_PREP[chunk];
    for (int i = tid; i < 2048; i += 256) {
        int row = i >> 4, q = i & 15;
        int nn = n0 + row;
        if (nn < N_NODES)
            *(float4*)&prep[(size_t)nn * 64 + q * 4] = *(float4*)&stage[row * PAD + q * 4];
    }
}

// ---------------- final_finish: sum partials + b1 + bx, tanh, @W2 + b2 ----------------
__global__ __launch_bounds__(256) void final_finish(
    const float* __restrict__ b1, const float* __restrict__ b2, float* __restrict__ out)
{
    extern __shared__ char sm[];
    __nv_bfloat16* Ah = (__nv_bfloat16*)sm;
    __nv_bfloat16* Al = Ah + 128 * ASTR;
    __nv_bfloat16* Bh = Al + 128 * ASTR;
    __nv_bfloat16* Bl = Bh + 64 * ASTR;
    float* stage = (float*)sm;

    const int n0  = blockIdx.x * 128;
    const int tid = threadIdx.x;
    const int wid = tid >> 5, lane = tid & 31, g = lane >> 2, t = lane & 3;

    for (int i = tid; i < 512; i += 256) {
        int row = i >> 3, c16 = (i & 7) * 16;
        *(uint4*)((char*)Bh + row * 144 + c16) =
            *(const uint4*)((const char*)g_W2H + row * 128 + c16);
        *(uint4*)((char*)Bl + row * 144 + c16) =
            *(const uint4*)((const char*)g_W2L + row * 128 + c16);
    }

    for (int i = tid; i < 2048; i += 256) {
        int row = i >> 4, k4 = (i & 15) * 4;
        int nn = n0 + row;
        float4 v = make_float4(0.f, 0.f, 0.f, 0.f);
        if (nn < N_NODES) {
            size_t off = (size_t)nn * 64 + k4;
#pragma unroll
            for (int c = 0; c < N_CHUNK; ++c) {
                float4 p = *(const float4*)&g_PREP[c][off];
                v.x += p.x; v.y += p.y; v.z += p.z; v.w += p.w;
            }
            float4 bb = *(const float4*)&b1[k4];
            float4 bx = *(const float4*)&g_bx[k4];
            v.x = tanhf(v.x + bb.x + bx.x); v.y = tanhf(v.y + bb.y + bx.y);
            v.z = tanhf(v.z + bb.z + bx.z); v.w = tanhf(v.w + bb.w + bx.w);
        }
        __nv_bfloat16 h0, l0, h1, l1, h2, l2, h3, l3;
        split1(v.x, h0, l0); split1(v.y, h1, l1);
        split1(v.z, h2, l2); split1(v.w, h3, l3);
        *(uint2*)((char*)Ah + row * 144 + k4 * 2) = make_uint2(pk(h0, h1), pk(h2, h3));
        *(uint2*)((char*)Al + row * 144 + k4 * 2) = make_uint2(pk(l0, l1), pk(l2, l3));
    }
    __syncthreads();

    float acc[8][4];
#pragma unroll
    for (int nt = 0; nt < 8; ++nt)
#pragma unroll
        for (int q = 0; q < 4; ++q) acc[nt][q] = 0.f;

    warp_mma_3term(Ah, Al, Bh, Bl, wid * 16, g, t, acc);
    __syncthreads();

    acc_to_stage(stage, acc, wid * 16, g, t);
    __syncthreads();

    for (int i = tid; i < 2048; i += 256) {
        int row = i >> 4, q = i & 15;
        int nn = n0 + row;
        if (nn < N_NODES) {
            float4 v  = *(float4*)&stage[row * PAD + q * 4];
            float4 bb = *(const float4*)&b2[q * 4];
            *(float4*)&out[(size_t)nn * 64 + q * 4] =
                make_float4(v.x + bb.x, v.y + bb.y, v.z + bb.z, v.w + bb.w);
        }
    }
}

// ---------------- launch ----------------
extern "C" void kernel_launch(void* const* d_in, const int* in_sizes, int n_in,
                              void* d_out, int out_size) {
    const float* emb     = (const float*)d_in[0];
    const float* W       = (const float*)d_in[1];
    const float* att_src = (const float*)d_in[2];
    const float* att_dst = (const float*)d_in[3];
    const float* bias    = (const float*)d_in[4];
    const float* W1      = (const float*)d_in[5];
    const float* b1      = (const float*)d_in[6];
    const float* W2      = (const float*)d_in[7];
    const float* b2      = (const float*)d_in[8];
    const int*   edges   = (const int*)d_in[9];
    const int*   nodes   = (const int*)d_in[10];
    float*       out     = (float*)d_out;

    const int MMA_SMEM = (128 * ASTR + 128 * ASTR + 64 * ASTR + 64 * ASTR) * 2;  // 55296
    cudaFuncSetAttribute(final_acc,    cudaFuncAttributeMaxDynamicSharedMemorySize, MMA_SMEM);
    cudaFuncSetAttribute(final_finish, cudaFuncAttributeMaxDynamicSharedMemorySize, MMA_SMEM);

    void *pCNT = nullptr, *pBX = nullptr;
    cudaGetSymbolAddress(&pCNT, g_cnt);
    cudaGetSymbolAddress(&pBX, g_bx);
    cudaMemsetAsync(pCNT, 0, sizeof(int) * N_REL * N_NODES, 0);
    cudaMemsetAsync(pBX,  0, 64 * sizeof(float), 0);

    prep_all<<<N_REL + 1, 256>>>(W, W1, W2, att_src, att_dst, bias);

    dim3 gsd((N_NODES * 4 + 255) / 256, N_REL);
    s_den<<<gsd, 256>>>(emb);

    dim3 gf((N_EDGE + 255) / 256, N_REL);
    fill_kernel<<<gf, 256>>>(edges);

    dim3 gn((N_NODES + 31) / 32, N_REL);
    gather_kernel<<<gn, 256>>>(emb);

    const int nb = (N_NODES + 127) / 128;   // 235
    dim3 gacc(nb, N_CHUNK);
    final_acc<<<gacc, 256, MMA_SMEM>>>(emb, nodes);
    final_finish<<<nb, 256, MMA_SMEM>>>(b1, b2, out);
}